// round 17
// baseline (speedup 1.0000x reference)
#include <cuda_runtime.h>
#include <mma.h>
#include <cstdint>

using namespace nvcuda;

#define SCALE 0.17677669529663687f  // 1/sqrt(32)

__device__ float g_relbias[4 * 64 * 64];
__device__ float g_wts[65536];   // tf32-rounded [SCALE*Wq | Wk | Wv | Wo]
__device__ float g_qh[67108864]; // [524288][128] q-proj (scale folded), rounded
__device__ float g_k [67108864];
__device__ float g_v [67108864];

__device__ __forceinline__ float rnd32(float x) {
    float r;
    asm("cvt.rna.tf32.f32 %0, %1;" : "=f"(r) : "f"(x));
    return r;
}

__global__ void relbias_kernel(const float* __restrict__ bias_table) {
    int idx = blockIdx.x * blockDim.x + threadIdx.x;
    if (idx < 4 * 64 * 64) {
        int h = idx >> 12;
        int n = (idx >> 6) & 63;
        int m = idx & 63;
        int r = ((n >> 3) - (m >> 3) + 7) * 15 + ((n & 7) - (m & 7) + 7);
        g_relbias[idx] = bias_table[r * 4 + h];
    }
}

__global__ void roundwts_kernel(const float* __restrict__ Wq,
                                const float* __restrict__ Wkv,
                                const float* __restrict__ Wo) {
    int idx = blockIdx.x * blockDim.x + threadIdx.x;
    if (idx < 16384)       g_wts[idx] = rnd32(Wq[idx] * SCALE);
    else if (idx < 49152)  g_wts[idx] = rnd32(Wkv[idx - 16384]);
    else if (idx < 65536)  g_wts[idx] = rnd32(Wo[idx - 49152]);
}

// raw tf32 mma: D(m16n8) += A(m16k8) * B(k8n8)
__device__ __forceinline__ void mma168(float& c0, float& c1, float& c2, float& c3,
                                       uint32_t a0, uint32_t a1, uint32_t a2, uint32_t a3,
                                       uint32_t b0, uint32_t b1) {
    asm volatile(
        "mma.sync.aligned.m16n8k8.row.col.f32.tf32.tf32.f32 "
        "{%0,%1,%2,%3}, {%4,%5,%6,%7}, {%8,%9}, {%0,%1,%2,%3};"
        : "+f"(c0), "+f"(c1), "+f"(c2), "+f"(c3)
        : "r"(a0), "r"(a1), "r"(a2), "r"(a3), "r"(b0), "r"(b1));
}

// ldmatrix x4: full m16k8 tf32 A fragment in one instruction (map verified R15/R16).
__device__ __forceinline__ void ldsm_x4(uint32_t& a0, uint32_t& a1, uint32_t& a2, uint32_t& a3,
                                        uint32_t addr) {
    asm volatile("ldmatrix.sync.aligned.m8n8.x4.shared.b16 {%0,%1,%2,%3}, [%4];"
                 : "=r"(a0), "=r"(a1), "=r"(a2), "=r"(a3) : "r"(addr));
}

// ============= projections: C[256 rows,128] = A @ W^T  (512 thr, 16 warps x n8 strip) =============
__global__ void __launch_bounds__(512, 2)
mm3_kernel(const float* __restrict__ q, const float* __restrict__ kv,
           const float* __restrict__ bq, const float* __restrict__ bkv) {
    __shared__ float sA[2][32 * 132];

    const int tid = threadIdx.x;
    const int w = tid >> 5;
    const int lane = tid & 31;
    const int g = lane >> 2;
    const int tig = lane & 3;
    const int n0 = w * 8;
    const int cc = n0 + 2 * tig;

    const float* src; const float* Wg; const float* bias; float* dst; float scl;
    {
        int m = blockIdx.x % 3;          // interleave q/k/v -> kv L2 reuse
        if (m == 0)      { src = q;  Wg = g_wts;         bias = bq;        dst = g_qh; scl = SCALE; }
        else if (m == 1) { src = kv; Wg = g_wts + 16384; bias = bkv;       dst = g_k;  scl = 1.0f; }
        else             { src = kv; Wg = g_wts + 32768; bias = bkv + 128; dst = g_v;  scl = 1.0f; }
    }
    const size_t row0 = (size_t)(blockIdx.x / 3) * 256;

    const float bias0 = bias[cc] * scl;
    const float bias1 = bias[cc + 1] * scl;

    uint32_t B[16][2];
#pragma unroll
    for (int kk = 0; kk < 16; kk++) {
        B[kk][0] = __float_as_uint(Wg[(n0 + g) * 128 + kk * 8 + tig]);
        B[kk][1] = __float_as_uint(Wg[(n0 + g) * 128 + kk * 8 + tig + 4]);
    }

    const uint32_t abase = (uint32_t)__cvta_generic_to_shared(sA)
                         + (uint32_t)((lane & 15) * 132 + (lane >> 4) * 4) * 4u;

    {
        const float4* s4 = (const float4*)(src + row0 * 128);
#pragma unroll
        for (int u = 0; u < 2; u++) {
            int i = tid + 512 * u;
            float4 v = s4[i];
            v.x = rnd32(v.x); v.y = rnd32(v.y); v.z = rnd32(v.z); v.w = rnd32(v.w);
            *(float4*)(sA[0] + (i >> 5) * 132 + (i & 31) * 4) = v;
        }
    }
    __syncthreads();

    for (int j = 0; j < 8; j++) {
        float4 pf0, pf1;
        if (j < 7) {
            const float4* n4 = (const float4*)(src + (row0 + (size_t)(j + 1) * 32) * 128);
            pf0 = n4[tid];
            pf1 = n4[tid + 512];
        }

        const uint32_t bufa = abase + (uint32_t)(j & 1) * 16896u;
        float c00 = bias0, c01 = bias1, c02 = bias0, c03 = bias1;
        float c10 = bias0, c11 = bias1, c12 = bias0, c13 = bias1;
#pragma unroll
        for (int kk = 0; kk < 16; kk++) {
            uint32_t a0, a1, a2, a3;
            ldsm_x4(a0, a1, a2, a3, bufa + kk * 32u);
            mma168(c00, c01, c02, c03, a0, a1, a2, a3, B[kk][0], B[kk][1]);
            uint32_t a4, a5, a6, a7;
            ldsm_x4(a4, a5, a6, a7, bufa + 8448u + kk * 32u);
            mma168(c10, c11, c12, c13, a4, a5, a6, a7, B[kk][0], B[kk][1]);
        }

        c00 = rnd32(c00); c01 = rnd32(c01); c02 = rnd32(c02); c03 = rnd32(c03);
        c10 = rnd32(c10); c11 = rnd32(c11); c12 = rnd32(c12); c13 = rnd32(c13);
        const size_t rb = row0 + (size_t)j * 32;
        *(float2*)(dst + (rb + g) * 128 + cc)      = make_float2(c00, c01);
        *(float2*)(dst + (rb + g + 8) * 128 + cc)  = make_float2(c02, c03);
        *(float2*)(dst + (rb + 16 + g) * 128 + cc) = make_float2(c10, c11);
        *(float2*)(dst + (rb + 24 + g) * 128 + cc) = make_float2(c12, c13);

        if (j < 7) {
            float* nb = sA[(j + 1) & 1];
#pragma unroll
            for (int u = 0; u < 2; u++) {
                int i = tid + 512 * u;
                float4 v = (u == 0) ? pf0 : pf1;
                v.x = rnd32(v.x); v.y = rnd32(v.y); v.z = rnd32(v.z); v.w = rnd32(v.w);
                *(float4*)(nb + (i >> 5) * 132 + (i & 31) * 4) = v;
            }
        }
        __syncthreads();
    }
}

// ========== fused attention + out-proj: 1 CTA/window, 512 thr, 16 warps (4/head) ==========
// dyn smem (floats): [0:8448) sQH | [8448:16896) sK | [16896:17408) pad | [17408:25856) sV
// overlays: Ph = 4 heads x 64x68 on [0:17408); x (64x132) on [0:8448) after PV.
using FragA  = wmma::fragment<wmma::matrix_a, 16, 16, 8, wmma::precision::tf32, wmma::row_major>;
using FragBR = wmma::fragment<wmma::matrix_b, 16, 16, 8, wmma::precision::tf32, wmma::row_major>;
using FragC  = wmma::fragment<wmma::accumulator, 16, 16, 8, float>;

__global__ void __launch_bounds__(512, 2)
attn_kernel(const float* __restrict__ mask, const float* __restrict__ bo,
            float* __restrict__ out) {
    extern __shared__ float smA[];
    float* sQH = smA;
    float* sK  = smA + 8448;
    float* sV  = smA + 17408;

    const int b = blockIdx.x;
    const int tid = threadIdx.x;
    const int w = tid >> 5;
    const int lane = tid & 31;
    const int g = lane >> 2;
    const int tig = lane & 3;
    const int h = w >> 2;
    const int sub = w & 3;

    // stage full-window qh/k/v (stride 132)
    {
        const float4* qs = (const float4*)(g_qh + (size_t)b * 8192);
        const float4* ks = (const float4*)(g_k + (size_t)b * 8192);
        const float4* vs = (const float4*)(g_v + (size_t)b * 8192);
#pragma unroll
        for (int u = 0; u < 4; u++) {
            int i = tid + 512 * u;
            int r = i >> 5, c4 = i & 31;
            *(float4*)(sQH + r * 132 + c4 * 4) = qs[i];
            *(float4*)(sK + r * 132 + c4 * 4) = ks[i];
            *(float4*)(sV + r * 132 + c4 * 4) = vs[i];
        }
    }
    __syncthreads();

    // ---- S = qh_h @ k_h^T (K=32), raw mma: warp owns rows sub*16..+15, 8 n8 tiles ----
    float sc[8][4];
#pragma unroll
    for (int t = 0; t < 8; t++) { sc[t][0] = 0.f; sc[t][1] = 0.f; sc[t][2] = 0.f; sc[t][3] = 0.f; }

    const uint32_t qbase = (uint32_t)__cvta_generic_to_shared(sQH)
                         + (uint32_t)((lane & 15) * 132 + (lane >> 4) * 4) * 4u
                         + (uint32_t)(sub * 16) * 528u + (uint32_t)h * 128u;
#pragma unroll
    for (int kc = 0; kc < 4; kc++) {
        uint32_t a0, a1, a2, a3;
        ldsm_x4(a0, a1, a2, a3, qbase + kc * 32u);
        const float* kb = sK + h * 32 + kc * 8 + tig;
#pragma unroll
        for (int t = 0; t < 8; t++) {
            uint32_t b0 = __float_as_uint(kb[(t * 8 + g) * 132]);
            uint32_t b1 = __float_as_uint(kb[(t * 8 + g) * 132 + 4]);
            mma168(sc[t][0], sc[t][1], sc[t][2], sc[t][3], a0, a1, a2, a3, b0, b1);
        }
    }

    // ---- softmax in registers (no max-shift; validated R12-R16) ----
    {
        const int nlo = sub * 16 + g;
        const float* rbp = g_relbias + h * 4096;
        const float* mkp = mask + (size_t)(b & 4095) * 4096;
        float slo = 0.f, shi = 0.f;
#pragma unroll
        for (int t = 0; t < 8; t++) {
            const int c = t * 8 + 2 * tig;
            float2 r0 = *(const float2*)(rbp + nlo * 64 + c);
            float2 m0 = *(const float2*)(mkp + nlo * 64 + c);
            float2 r1 = *(const float2*)(rbp + (nlo + 8) * 64 + c);
            float2 m1 = *(const float2*)(mkp + (nlo + 8) * 64 + c);
            sc[t][0] = __expf(sc[t][0] + r0.x + m0.x);
            sc[t][1] = __expf(sc[t][1] + r0.y + m0.y);
            sc[t][2] = __expf(sc[t][2] + r1.x + m1.x);
            sc[t][3] = __expf(sc[t][3] + r1.y + m1.y);
            slo += sc[t][0] + sc[t][1];
            shi += sc[t][2] + sc[t][3];
        }
        slo += __shfl_xor_sync(0xffffffffu, slo, 1);
        slo += __shfl_xor_sync(0xffffffffu, slo, 2);
        shi += __shfl_xor_sync(0xffffffffu, shi, 1);
        shi += __shfl_xor_sync(0xffffffffu, shi, 2);
        float ilo = 1.0f / slo, ihi = 1.0f / shi;
#pragma unroll
        for (int t = 0; t < 8; t++) {
            sc[t][0] = rnd32(sc[t][0] * ilo);
            sc[t][1] = rnd32(sc[t][1] * ilo);
            sc[t][2] = rnd32(sc[t][2] * ihi);
            sc[t][3] = rnd32(sc[t][3] * ihi);
        }
    }
    __syncthreads();   // all warps done reading sQH/sK -> overlay Ph

    // store P (head h region: 64x68 at smA + h*4352)
    float* php = smA + h * 4352;
    {
        float* plo = php + (sub * 16 + g) * 68 + 2 * tig;
        float* phi = php + (sub * 16 + g + 8) * 68 + 2 * tig;
#pragma unroll
        for (int t = 0; t < 8; t++) {
            *(float2*)(plo + t * 8) = make_float2(sc[t][0], sc[t][1]);
            *(float2*)(phi + t * 8) = make_float2(sc[t][2], sc[t][3]);
        }
    }
    __syncwarp();      // PV reads only this warp's rows

    // ---- x_h = P_h @ v_h (K=64, B row-major) ----
    FragC xc[2];
#pragma unroll
    for (int t = 0; t < 2; t++) wmma::fill_fragment(xc[t], 0.0f);
#pragma unroll
    for (int k = 0; k < 64; k += 8) {
        FragA a;
        wmma::load_matrix_sync(a, php + sub * 16 * 68 + k, 68);
#pragma unroll
        for (int t = 0; t < 2; t++) {
            FragBR bf;
            wmma::load_matrix_sync(bf, sV + h * 32 + k * 132 + t * 16, 132);
            wmma::mma_sync(xc[t], a, bf, xc[t]);
        }
    }
    __syncthreads();   // all PV reads of Ph/sV done -> overlay x on [0:8448)

#pragma unroll
    for (int t = 0; t < 2; t++) {
#pragma unroll
        for (int i = 0; i < xc[t].num_elements; i++) xc[t].x[i] = rnd32(xc[t].x[i]);
        wmma::store_matrix_sync(smA + sub * 16 * 132 + h * 32 + t * 16, xc[t], 132, wmma::mem_row_major);
    }
    __syncthreads();

    // ---- out = x @ Wo^T + bo (mm3 inner loop; A = smem x via ldsm, B in regs) ----
    {
        const float* Wg = g_wts + 49152;
        const int n0 = w * 8;
        const int cc = n0 + 2 * tig;
        uint32_t B[16][2];
#pragma unroll
        for (int kk = 0; kk < 16; kk++) {
            B[kk][0] = __float_as_uint(Wg[(n0 + g) * 128 + kk * 8 + tig]);
            B[kk][1] = __float_as_uint(Wg[(n0 + g) * 128 + kk * 8 + tig + 4]);
        }
        const float bias0 = bo[cc];
        const float bias1 = bo[cc + 1];
        const uint32_t abase = (uint32_t)__cvta_generic_to_shared(smA)
                             + (uint32_t)((lane & 15) * 132 + (lane >> 4) * 4) * 4u;
        float* od = out + (size_t)b * 8192;
#pragma unroll
        for (int rp = 0; rp < 2; rp++) {
            const uint32_t rpb = abase + (uint32_t)rp * 16896u;   // +32 rows
            float c00 = bias0, c01 = bias1, c02 = bias0, c03 = bias1;
            float c10 = bias0, c11 = bias1, c12 = bias0, c13 = bias1;
#pragma unroll
            for (int kk = 0; kk < 16; kk++) {
                uint32_t a0, a1, a2, a3;
                ldsm_x4(a0, a1, a2, a3, rpb + kk * 32u);
                mma168(c00, c01, c02, c03, a0, a1, a2, a3, B[kk][0], B[kk][1]);
                uint32_t a4, a5, a6, a7;
                ldsm_x4(a4, a5, a6, a7, rpb + 8448u + kk * 32u);
                mma168(c10, c11, c12, c13, a4, a5, a6, a7, B[kk][0], B[kk][1]);
            }
            const int rb = rp * 32;
            *(float2*)(od + (rb + g) * 128 + cc)      = make_float2(c00, c01);
            *(float2*)(od + (rb + g + 8) * 128 + cc)  = make_float2(c02, c03);
            *(float2*)(od + (rb + 16 + g) * 128 + cc) = make_float2(c10, c11);
            *(float2*)(od + (rb + 24 + g) * 128 + cc) = make_float2(c12, c13);
        }
    }
}

extern "C" void kernel_launch(void* const* d_in, const int* in_sizes, int n_in,
                              void* d_out, int out_size) {
    const float* q          = (const float*)d_in[0];
    const float* kv         = (const float*)d_in[1];
    const float* mask       = (const float*)d_in[2];
    const float* Wq         = (const float*)d_in[3];
    const float* bq         = (const float*)d_in[4];
    const float* Wkv        = (const float*)d_in[5];
    const float* bkv        = (const float*)d_in[6];
    const float* Wo         = (const float*)d_in[7];
    const float* bo         = (const float*)d_in[8];
    const float* bias_table = (const float*)d_in[9];
    float* out = (float*)d_out;

    relbias_kernel<<<64, 256>>>(bias_table);
    roundwts_kernel<<<256, 256>>>(Wq, Wkv, Wo);

    mm3_kernel<<<6144, 512>>>(q, kv, bq, bkv);           // qh, k, v projections

    const int smem_attn = 25856 * 4;                     // 101 KB
    cudaFuncSetAttribute(attn_kernel, cudaFuncAttributeMaxDynamicSharedMemorySize, smem_attn);
    attn_kernel<<<8192, 512, smem_attn>>>(mask, bo, out);  // attention + out-proj fused
}